// round 13
// baseline (speedup 1.0000x reference)
#include <cuda_runtime.h>
#include <cuda_bf16.h>

typedef unsigned int u32;
typedef unsigned long long u64;
typedef unsigned char u8;

#define DIM 64
#define NHID 256
#define W0_SZ (DIM*NHID)
#define W1_SZ (NHID*NHID)
#define W2_SZ (NHID*DIM)
#define WNET  (W0_SZ+W1_SZ+W2_SZ)

#define TBR 32
#define NTHREADS 128

#define GRP_PAIR 98304
#define GRP_STRIDE ((size_t)32*GRP_PAIR)

#define SM_AHI 0u          /* 32 x 512B swizzled bf16 tile */
#define SM_ALO 16384u
#define SM_LOC 32768u      /* 32 x 66 fp32 */
#define SM_Y   41216u
#define SM_TOTAL 49664u

// PART[wn][g] packed as nibbles: band owned by (wn,g);  g == band>>2
#define PARTPACK 0xC963D872EB41FA50ull
#define WNOFPACK 0x0123103223013210ull

__device__ __align__(16) unsigned char g_W[(size_t)4*GRP_STRIDE + 4096];
__device__ __align__(16) float g_B[32*512];
__device__ u32 g_act0[2][2];   // bits: kc*16+band (kc<4)
__device__ u32 g_act1[8];      // bits: kc*16+band (kc<16)
__device__ u32 g_act2[2][4];   // bits: kc*8+B     (kc<16)

// compacted block lists + slot maps (built by compact_kernel)
__device__ __align__(4) u8 g_list0[2][4][20];
__device__ __align__(4) u8 g_n0[2][4][4];
__device__ __align__(4) u8 g_list1[4][68];
__device__ __align__(4) u8 g_n1[4][4];
__device__ __align__(4) u8 g_list2[2][4][36];
__device__ __align__(4) u8 g_n2[2][4][2];
__device__ __align__(4) u8 g_slot0[2][4][16];
__device__ __align__(4) u8 g_slot1[4][64];
__device__ __align__(4) u8 g_slot2[2][4][32];

static __device__ __forceinline__ int rank256(int i){
    int v = i % 63, m = i / 63;
    return (v < 4 ? v*5 : 20 + (v-4)*4) + m;
}
static __device__ __forceinline__ u32 s2u(const void* p){
  u32 a; asm("{ .reg .u64 t; cvta.to.shared.u64 t, %1; cvt.u32.u64 %0, t; }":"=r"(a):"l"(p)); return a;
}
static __device__ __forceinline__ void ldsm4(u32* r, u32 a){
  asm volatile("ldmatrix.sync.aligned.m8n8.x4.shared.b16 {%0,%1,%2,%3}, [%4];"
    :"=r"(r[0]),"=r"(r[1]),"=r"(r[2]),"=r"(r[3]):"r"(a));
}
static __device__ __forceinline__ void mma_bf16(float* d, const u32* a, const u32* b){
  asm volatile("mma.sync.aligned.m16n8k16.row.col.f32.bf16.bf16.f32 "
    "{%0,%1,%2,%3}, {%4,%5,%6,%7}, {%8,%9}, {%0,%1,%2,%3};"
    :"+f"(d[0]),"+f"(d[1]),"+f"(d[2]),"+f"(d[3])
    :"r"(a[0]),"r"(a[1]),"r"(a[2]),"r"(a[3]),"r"(b[0]),"r"(b[1]));
}
static __device__ __forceinline__ u32 packbf(float lo, float hi){
  u32 r; asm("cvt.rn.bf16x2.f32 %0, %1, %2;":"=r"(r):"f"(hi),"f"(lo)); return r;
}
static __device__ __forceinline__ void writeA2(unsigned char* smp, int row, int c, float v0, float v1){
  u32 unit = (u32)c >> 3;
  u32 off = (u32)row*512u + (((unit ^ ((u32)row & 7u)) << 4) | (((u32)c & 7u) << 1));
  u32 h = packbf(v0, v1);
  float h0 = __uint_as_float(h << 16);
  float h1 = __uint_as_float(h & 0xFFFF0000u);
  u32 lo = packbf(v0 - h0, v1 - h1);
  *(u32*)(smp + SM_AHI + off) = h;
  *(u32*)(smp + SM_ALO + off) = lo;
}

// ---------- meta: permuted biases + exact block-activity bitmasks ------------
__global__ void meta_kernel(
    const float* __restrict__ lb0, const float* __restrict__ lb1,
    const float* __restrict__ sb0, const float* __restrict__ sb1,
    const float* __restrict__ M0,  const float* __restrict__ M1,
    const float* __restrict__ M2)
{
    int idx = blockIdx.x*blockDim.x + threadIdx.x;
    if (idx < 16384){
        int pair = idx >> 9, j = idx & 511;
        int l = pair >> 1, net = pair & 1;
        if (j < 256){
            g_B[pair*512 + rank256(j)] = (net ? sb0 : lb0)[l*NHID + j];
        } else {
            int jj = j - 256;
            g_B[pair*512 + 256 + rank256(jj)] = (net ? sb1 : lb1)[l*NHID + jj];
        }
        return;
    }
    int t = idx - 16384;
    if (t < 32768){
        int par = t >> 14, r = t & 16383;
        int n = r >> 6, k = r & 63;
        if (M0[par*W0_SZ + n*64 + k] != 0.f){
            int bit = (k >> 4)*16 + (rank256(n) >> 4);
            atomicOr(&g_act0[par][bit >> 5], 1u << (bit & 31));
        }
        return;
    }
    t -= 32768;
    if (t < 65536){
        int n = t >> 8, k = t & 255;
        if (M1[n*256 + k] != 0.f){
            int bit = (rank256(k) >> 4)*16 + (rank256(n) >> 4);
            atomicOr(&g_act1[bit >> 5], 1u << (bit & 31));
        }
        return;
    }
    t -= 65536;
    {
        int par = t >> 14, r = t & 16383;
        int n = r >> 8, k = r & 255;
        if (M2[par*W2_SZ + n*256 + k] != 0.f){
            int v = par ? 63 - n : n;
            int bit = (rank256(k) >> 4)*8 + (v >> 3);
            atomicOr(&g_act2[par][bit >> 5], 1u << (bit & 31));
        }
    }
}

// ---------- compact: build sorted block lists + slot maps (1 thread) ---------
__global__ void compact_kernel()
{
    if (threadIdx.x || blockIdx.x) return;
    for (int wn = 0; wn < 4; wn++){
        int pos = 0, top = 63;
        for (int g = 0; g < 4; g++){
            int band = (int)((PARTPACK >> ((wn*4+g)*4)) & 15);
            int c = 0;
            for (int kc = 0; kc < 16; kc++){
                int bit = kc*16 + band, idx = kc*4 + g;
                if ((g_act1[bit>>5] >> (bit&31)) & 1){
                    g_list1[wn][pos] = (u8)(kc | (g<<6));
                    g_slot1[wn][idx] = (u8)pos; pos++; c++;
                } else g_slot1[wn][idx] = (u8)(top--);
            }
            g_n1[wn][g] = (u8)c;
        }
        for (int par = 0; par < 2; par++){
            pos = 0; top = 15;
            for (int g = 0; g < 4; g++){
                int band = (int)((PARTPACK >> ((wn*4+g)*4)) & 15);
                int c = 0;
                for (int kc = 0; kc < 4; kc++){
                    int bit = kc*16 + band, idx = kc*4 + g;
                    if ((g_act0[par][bit>>5] >> (bit&31)) & 1){
                        g_list0[par][wn][pos] = (u8)(kc | (g<<6));
                        g_slot0[par][wn][idx] = (u8)pos; pos++; c++;
                    } else g_slot0[par][wn][idx] = (u8)(top--);
                }
                g_n0[par][wn][g] = (u8)c;
            }
            pos = 0; top = 31;
            for (int tt = 0; tt < 2; tt++){
                int B = tt ? 7-wn : wn;
                int c = 0;
                for (int kc = 0; kc < 16; kc++){
                    int bit = kc*8 + B, idx = kc*2 + tt;
                    if ((g_act2[par][bit>>5] >> (bit&31)) & 1){
                        g_list2[par][wn][pos] = (u8)(kc | (tt<<6));
                        g_slot2[par][wn][idx] = (u8)pos; pos++; c++;
                    } else g_slot2[par][wn][idx] = (u8)(top--);
                }
                g_n2[par][wn][tt] = (u8)c;
            }
        }
    }
}

// ---------- prep: mask, bf16 hi/lo split, compacted fragment image -----------
__global__ void prep_kernel(
    const float* __restrict__ lW0, const float* __restrict__ lW1, const float* __restrict__ lW2,
    const float* __restrict__ sW0, const float* __restrict__ sW1, const float* __restrict__ sW2,
    const float* __restrict__ M0,  const float* __restrict__ M1,  const float* __restrict__ M2)
{
    int idx = blockIdx.x*blockDim.x + threadIdx.x;
    if (idx >= 32*WNET) return;
    int pair = idx / WNET, off = idx % WNET;
    int l = pair >> 1, net = pair & 1, par = l & 1;
    float w; int wn, itemoff, lodelta, kl, din;
    if (off < W0_SZ){
        int n = off >> 6, k = off & 63;
        int s = l*W0_SZ + off;
        w = (net ? sW0[s] : lW0[s]) * M0[s];
        int nr = rank256(n); int band = nr >> 4;
        wn = (int)((WNOFPACK >> (band*4)) & 15);
        int g = band >> 2;
        int nn = nr & 15, tt = nn >> 3, nrow = nn & 7;
        int kc = k >> 4; kl = k & 15;
        int slot = g_slot0[par][wn][kc*4+g];
        itemoff = slot*1024; lodelta = 512;
        int T = (nrow << 2) | ((kl & 7) >> 1);
        int b = (tt << 1) | (kl >> 3);
        din = T*16 + b*4 + ((kl & 1) << 1);
    } else if (off < W0_SZ + W1_SZ){
        int o = off - W0_SZ;
        int n = o >> 8, k = o & 255;
        int s = l*W1_SZ + o;
        w = (net ? sW1[s] : lW1[s]) * M1[s];
        int nr = rank256(n); int band = nr >> 4;
        wn = (int)((WNOFPACK >> (band*4)) & 15);
        int g = band >> 2;
        int nn = nr & 15, tt = nn >> 3, nrow = nn & 7;
        int kr = rank256(k);
        int kc = kr >> 4; kl = kr & 15;
        int slot = g_slot1[wn][kc*4+g];
        itemoff = 16384 + slot*1024; lodelta = 512;
        int T = (nrow << 2) | ((kl & 7) >> 1);
        int b = (tt << 1) | (kl >> 3);
        din = T*16 + b*4 + ((kl & 1) << 1);
    } else {
        int o = off - W0_SZ - W1_SZ;
        int n = o >> 8, k = o & 255;
        int s = l*W2_SZ + o;
        w = (net ? sW2[s] : lW2[s]) * M2[s];
        int v = par ? 63 - n : n;
        int B = v >> 3;
        wn = (B < 4) ? B : 7 - B;
        int tt = (B < 4) ? 0 : 1;
        int nrow = v & 7;
        int kr = rank256(k);
        int kc = kr >> 4; kl = kr & 15;
        int slot = g_slot2[par][wn][kc*2+tt];
        itemoff = 81920 + slot*512; lodelta = 256;
        int T = (nrow << 2) | ((kl & 7) >> 1);
        din = T*8 + (kl >> 3)*4 + ((kl & 1) << 1);
    }
    size_t dst = (size_t)wn*GRP_STRIDE + (size_t)pair*GRP_PAIR + itemoff + din;
    __nv_bfloat16 hv = __float2bfloat16_rn(w);
    __nv_bfloat16 lv = __float2bfloat16_rn(w - __bfloat162float(hv));
    *(__nv_bfloat16*)(g_W + dst) = hv;
    *(__nv_bfloat16*)(g_W + dst + lodelta) = lv;
}

// ---------------- fused flow kernel ------------------------------------------
__global__ void __launch_bounds__(NTHREADS,4) flow_kernel(
    const float* __restrict__ u,
    const float* __restrict__ lb2, const float* __restrict__ sb2,
    float* __restrict__ out)
{
    extern __shared__ unsigned char smp[];
    u32 smb = s2u(smp);
    int tid = threadIdx.x, lane = tid & 31, wn = tid >> 5;
    int q = lane >> 3, ln = lane & 7;
    int row0 = blockIdx.x * TBR;
    float* loc_sm = (float*)(smp + SM_LOC);
    float* y_sm   = (float*)(smp + SM_Y);

    int r0 = lane >> 2;                // rows 0..7 (+i*16, +rr*8 → 0..31)
    int lc2 = (lane & 3)*2;

    const unsigned char* tb  = g_W + (size_t)wn*GRP_STRIDE + (size_t)lane*16;
    const unsigned char* tb2 = g_W + (size_t)wn*GRP_STRIDE + (size_t)lane*8;

    // init y (feature space): y_sm + A tiles
    #pragma unroll
    for (int i = 0; i < 2; i++)
      #pragma unroll
      for (int j = 0; j < 2; j++)
        #pragma unroll
        for (int rr = 0; rr < 2; rr++){
          int row = r0 + i*16 + rr*8;
          int c = wn*16 + j*8 + lc2;
          float2 v = *(const float2*)(u + (size_t)(row0 + row)*DIM + c);
          *(float2*)&y_sm[row*66 + c] = v;
          writeA2(smp, row, c, v.x, v.y);
        }
    __syncthreads();

    u32 nn1 = *(const u32*)&g_n1[wn][0];
    const u8* l1p = &g_list1[wn][0];

    float acc[16][4];
    auto zacc = [&](){
        #pragma unroll
        for (int t = 0; t < 16; t++){ acc[t][0]=0.f; acc[t][1]=0.f; acc[t][2]=0.f; acc[t][3]=0.f; }
    };
    auto ldA = [&](u32 base, int kc, u32 (*r)[4]){
        u32 arow0 = (u32)(((q & 1) << 3) + ln);
        u32 aunit = (u32)(kc*2 + (q >> 1));
        #pragma unroll
        for (int i = 0; i < 2; i++){
            u32 rr = arow0 + (u32)i*16u;
            u32 aoff = rr*512u + ((aunit ^ (rr & 7u)) << 4);
            ldsm4(r[i], base + aoff);
        }
    };

    #pragma unroll 1
    for (int pair = 0; pair < 32; pair++){
        int l = pair >> 1, net = pair & 1, par = l & 1;
        const float* Bs0 = g_B + pair*512;
        const float* Bs1 = Bs0 + 256;
        const float* b2 = (net ? sb2 : lb2) + l*DIM;
        const unsigned char* wp0 = tb  + (size_t)pair*GRP_PAIR;
        const unsigned char* wp2 = tb2 + (size_t)pair*GRP_PAIR + 81920;
        const u8* l0p = &g_list0[par][wn][0];
        const u8* l2p = &g_list2[par][wn][0];
        u32 nn0 = *(const u32*)&g_n0[par][wn][0];
        unsigned short nn2 = *(const unsigned short*)&g_n2[par][wn][0];

        uint4 bh4 = *(const uint4*)(wp0);
        u32 ent = l0p[0];

        // ---- stage0 (compacted, sorted by g) ----
        zacc();
        {
            int itb = 0;
            #pragma unroll
            for (int g = 0; g < 4; g++){
                int cnt = (int)((nn0 >> (g*8)) & 255u);
                #pragma unroll 1
                for (int t = 0; t < cnt; t++){
                    int it = itb + t;
                    int kc = (int)(ent & 15u);
                    u32 ah[2][4], al[2][4];
                    ldA(smb + SM_AHI, kc, ah);
                    uint4 bl4 = *(const uint4*)(wp0 + it*1024 + 512);
                    ldA(smb + SM_ALO, kc, al);
                    u32 bc[4] = {bh4.x, bh4.y, bh4.z, bh4.w};
                    ent = l0p[it+1];
                    #pragma unroll
                    for (int i = 0; i < 2; i++)
                      #pragma unroll
                      for (int tt = 0; tt < 2; tt++)
                        mma_bf16(acc[i*8 + g*2 + tt], ah[i], bc + tt*2);
                    #pragma unroll
                    for (int i = 0; i < 2; i++)
                      #pragma unroll
                      for (int tt = 0; tt < 2; tt++)
                        mma_bf16(acc[i*8 + g*2 + tt], al[i], bc + tt*2);
                    bh4 = *(const uint4*)(wp0 + (it+1)*1024);
                    u32 bd[4] = {bl4.x, bl4.y, bl4.z, bl4.w};
                    #pragma unroll
                    for (int i = 0; i < 2; i++)
                      #pragma unroll
                      for (int tt = 0; tt < 2; tt++)
                        mma_bf16(acc[i*8 + g*2 + tt], ah[i], bd + tt*2);
                }
                itb += cnt;
            }
        }
        bh4 = *(const uint4*)(wp0 + 16384);
        ent = l1p[0];
        __syncthreads();
        #pragma unroll
        for (int i = 0; i < 2; i++)
          #pragma unroll
          for (int j = 0; j < 8; j++){
            int g = j >> 1, tt = j & 1;
            int band = (int)((PARTPACK >> ((wn*4+g)*4)) & 15);
            int c = band*16 + tt*8 + lc2;
            float2 bb = *(const float2*)(Bs0 + c);
            float* d = acc[i*8 + j];
            writeA2(smp, r0 + i*16,     c, fmaxf(d[0]+bb.x,0.f), fmaxf(d[1]+bb.y,0.f));
            writeA2(smp, r0 + i*16 + 8, c, fmaxf(d[2]+bb.x,0.f), fmaxf(d[3]+bb.y,0.f));
          }
        __syncthreads();

        // ---- stage1 (compacted) ----
        zacc();
        {
            const unsigned char* w1 = wp0 + 16384;
            int itb = 0;
            #pragma unroll
            for (int g = 0; g < 4; g++){
                int cnt = (int)((nn1 >> (g*8)) & 255u);
                #pragma unroll 1
                for (int t = 0; t < cnt; t++){
                    int it = itb + t;
                    int kc = (int)(ent & 15u);
                    u32 ah[2][4], al[2][4];
                    ldA(smb + SM_AHI, kc, ah);
                    uint4 bl4 = *(const uint4*)(w1 + it*1024 + 512);
                    ldA(smb + SM_ALO, kc, al);
                    u32 bc[4] = {bh4.x, bh4.y, bh4.z, bh4.w};
                    ent = l1p[it+1];
                    #pragma unroll
                    for (int i = 0; i < 2; i++)
                      #pragma unroll
                      for (int tt = 0; tt < 2; tt++)
                        mma_bf16(acc[i*8 + g*2 + tt], ah[i], bc + tt*2);
                    #pragma unroll
                    for (int i = 0; i < 2; i++)
                      #pragma unroll
                      for (int tt = 0; tt < 2; tt++)
                        mma_bf16(acc[i*8 + g*2 + tt], al[i], bc + tt*2);
                    bh4 = *(const uint4*)(w1 + (it+1)*1024);
                    u32 bd[4] = {bl4.x, bl4.y, bl4.z, bl4.w};
                    #pragma unroll
                    for (int i = 0; i < 2; i++)
                      #pragma unroll
                      for (int tt = 0; tt < 2; tt++)
                        mma_bf16(acc[i*8 + g*2 + tt], ah[i], bd + tt*2);
                }
                itb += cnt;
            }
        }
        uint2 bh2 = *(const uint2*)(wp2);
        u32 ent2 = l2p[0];
        __syncthreads();
        #pragma unroll
        for (int i = 0; i < 2; i++)
          #pragma unroll
          for (int j = 0; j < 8; j++){
            int g = j >> 1, tt = j & 1;
            int band = (int)((PARTPACK >> ((wn*4+g)*4)) & 15);
            int c = band*16 + tt*8 + lc2;
            float2 bb = *(const float2*)(Bs1 + c);
            float* d = acc[i*8 + j];
            writeA2(smp, r0 + i*16,     c, fmaxf(d[0]+bb.x,0.f), fmaxf(d[1]+bb.y,0.f));
            writeA2(smp, r0 + i*16 + 8, c, fmaxf(d[2]+bb.x,0.f), fmaxf(d[3]+bb.y,0.f));
          }
        __syncthreads();

        // ---- stage2 (compacted, sorted by tt) ----
        zacc();
        {
            int itb = 0;
            #pragma unroll
            for (int tt = 0; tt < 2; tt++){
                int cnt = (int)((nn2 >> (tt*8)) & 255u);
                #pragma unroll 1
                for (int t = 0; t < cnt; t++){
                    int it = itb + t;
                    int kc = (int)(ent2 & 15u);
                    u32 ah[2][4], al[2][4];
                    ldA(smb + SM_AHI, kc, ah);
                    uint2 bl2 = *(const uint2*)(wp2 + it*512 + 256);
                    ldA(smb + SM_ALO, kc, al);
                    u32 bc[2] = {bh2.x, bh2.y};
                    ent2 = l2p[it+1];
                    #pragma unroll
                    for (int i = 0; i < 2; i++)
                        mma_bf16(acc[i*8 + tt], ah[i], bc);
                    #pragma unroll
                    for (int i = 0; i < 2; i++)
                        mma_bf16(acc[i*8 + tt], al[i], bc);
                    bh2 = *(const uint2*)(wp2 + (it+1)*512);
                    u32 bd[2] = {bl2.x, bl2.y};
                    #pragma unroll
                    for (int i = 0; i < 2; i++)
                        mma_bf16(acc[i*8 + tt], ah[i], bd);
                }
                itb += cnt;
            }
        }
        __syncthreads();
        #pragma unroll
        for (int i = 0; i < 2; i++)
          #pragma unroll
          for (int j = 0; j < 2; j++){
            int Bsel = j ? 7-wn : wn;
            int v = Bsel*8 + lc2;
            int f0 = par ? 63-v : v;
            int f1 = par ? 62-v : v+1;
            float bb0 = b2[f0], bb1 = b2[f1];
            float* d = acc[i*8 + j];
            #pragma unroll
            for (int rr = 0; rr < 2; rr++){
                int row = r0 + i*16 + rr*8;
                float s0 = d[rr*2]   + bb0;
                float s1 = d[rr*2+1] + bb1;
                if (net == 0){
                    loc_sm[row*66 + f0] = s0;
                    loc_sm[row*66 + f1] = s1;
                    int ce = par ? 62-v : v;
                    float ya = y_sm[row*66 + ce];
                    float yb = y_sm[row*66 + ce + 1];
                    writeA2(smp, row, ce, ya, yb);
                } else {
                    float y0 = expf(-s0) * (y_sm[row*66 + f0] - loc_sm[row*66 + f0]);
                    float y1 = expf(-s1) * (y_sm[row*66 + f1] - loc_sm[row*66 + f1]);
                    int ce = par ? 62-v : v;
                    float ca = par ? y1 : y0;
                    float cbv = par ? y0 : y1;
                    if (pair == 31){
                        *(float2*)(out + (size_t)(row0 + row)*DIM + ce) = make_float2(ca, cbv);
                    } else {
                        y_sm[row*66 + ce]     = ca;
                        y_sm[row*66 + ce + 1] = cbv;
                        writeA2(smp, row, ce, ca, cbv);
                    }
                }
            }
          }
        __syncthreads();
    }
}

// ---------------- launch ------------------------------------------------------
extern "C" void kernel_launch(void* const* d_in, const int* in_sizes, int n_in,
                              void* d_out, int out_size)
{
    const float* u   = (const float*)d_in[0];
    const float* lW0 = (const float*)d_in[1];
    const float* lb0 = (const float*)d_in[2];
    const float* lW1 = (const float*)d_in[3];
    const float* lb1 = (const float*)d_in[4];
    const float* lW2 = (const float*)d_in[5];
    const float* lb2 = (const float*)d_in[6];
    const float* sW0 = (const float*)d_in[7];
    const float* sb0 = (const float*)d_in[8];
    const float* sW1 = (const float*)d_in[9];
    const float* sb1 = (const float*)d_in[10];
    const float* sW2 = (const float*)d_in[11];
    const float* sb2 = (const float*)d_in[12];
    const float* M0  = (const float*)d_in[13];
    const float* M1  = (const float*)d_in[14];
    const float* M2  = (const float*)d_in[15];

    int rows = in_sizes[0] / DIM;

    cudaFuncSetAttribute(flow_kernel, cudaFuncAttributeMaxDynamicSharedMemorySize, SM_TOTAL);

    meta_kernel<<<(147456 + 255)/256, 256>>>(lb0, lb1, sb0, sb1, M0, M1, M2);
    compact_kernel<<<1, 32>>>();
    const int total = 32*WNET;
    prep_kernel<<<(total + 255)/256, 256>>>(lW0, lW1, lW2, sW0, sW1, sW2, M0, M1, M2);

    flow_kernel<<<rows / TBR, NTHREADS, SM_TOTAL>>>(u, lb2, sb2, (float*)d_out);
}

// round 14
// speedup vs baseline: 1.0817x; 1.0817x over previous
#include <cuda_runtime.h>
#include <cuda_bf16.h>

typedef unsigned int u32;
typedef unsigned long long u64;
typedef unsigned char u8;

#define DIM 64
#define NHID 256
#define W0_SZ (DIM*NHID)
#define W1_SZ (NHID*NHID)
#define W2_SZ (NHID*DIM)
#define WNET  (W0_SZ+W1_SZ+W2_SZ)

#define TBR 32
#define NTHREADS 128

#define GRP_PAIR 98304
#define GRP_STRIDE ((size_t)32*GRP_PAIR)

#define SM_AHI 0u
#define SM_ALO 16384u
#define SM_LOC 32768u
#define SM_Y   41216u
#define SM_TOTAL 49664u

#define PARTPACK 0xC963D872EB41FA50ull
#define WNOFPACK 0x0123103223013210ull

__device__ __align__(16) unsigned char g_W[(size_t)4*GRP_STRIDE + 4096];
__device__ __align__(16) float g_B[32*512];
__device__ u32 g_act0[2][2];
__device__ u32 g_act1[8];
__device__ u32 g_act2[2][4];

__device__ __align__(4) u8 g_list0[2][4][20];
__device__ __align__(4) u8 g_n0[2][4][4];
__device__ __align__(4) u8 g_list1[4][68];
__device__ __align__(4) u8 g_n1[4][4];
__device__ __align__(4) u8 g_list2[2][4][36];
__device__ __align__(4) u8 g_n2[2][4][2];
__device__ __align__(4) u8 g_slot0[2][4][16];
__device__ __align__(4) u8 g_slot1[4][64];
__device__ __align__(4) u8 g_slot2[2][4][32];

static __device__ __forceinline__ int rank256(int i){
    int v = i % 63, m = i / 63;
    return (v < 4 ? v*5 : 20 + (v-4)*4) + m;
}
static __device__ __forceinline__ u32 s2u(const void* p){
  u32 a; asm("{ .reg .u64 t; cvta.to.shared.u64 t, %1; cvt.u32.u64 %0, t; }":"=r"(a):"l"(p)); return a;
}
static __device__ __forceinline__ void ldsm4(u32* r, u32 a){
  asm volatile("ldmatrix.sync.aligned.m8n8.x4.shared.b16 {%0,%1,%2,%3}, [%4];"
    :"=r"(r[0]),"=r"(r[1]),"=r"(r[2]),"=r"(r[3]):"r"(a));
}
static __device__ __forceinline__ void mma_bf16(float* d, const u32* a, const u32* b){
  asm volatile("mma.sync.aligned.m16n8k16.row.col.f32.bf16.bf16.f32 "
    "{%0,%1,%2,%3}, {%4,%5,%6,%7}, {%8,%9}, {%0,%1,%2,%3};"
    :"+f"(d[0]),"+f"(d[1]),"+f"(d[2]),"+f"(d[3])
    :"r"(a[0]),"r"(a[1]),"r"(a[2]),"r"(a[3]),"r"(b[0]),"r"(b[1]));
}
static __device__ __forceinline__ u32 packbf(float lo, float hi){
  u32 r; asm("cvt.rn.bf16x2.f32 %0, %1, %2;":"=r"(r):"f"(hi),"f"(lo)); return r;
}
static __device__ __forceinline__ void writeA2(unsigned char* smp, int row, int c, float v0, float v1){
  u32 unit = (u32)c >> 3;
  u32 off = (u32)row*512u + (((unit ^ ((u32)row & 7u)) << 4) | (((u32)c & 7u) << 1));
  u32 h = packbf(v0, v1);
  float h0 = __uint_as_float(h << 16);
  float h1 = __uint_as_float(h & 0xFFFF0000u);
  u32 lo = packbf(v0 - h0, v1 - h1);
  *(u32*)(smp + SM_AHI + off) = h;
  *(u32*)(smp + SM_ALO + off) = lo;
}

// ---------- meta: permuted biases + exact block-activity bitmasks ------------
__global__ void meta_kernel(
    const float* __restrict__ lb0, const float* __restrict__ lb1,
    const float* __restrict__ sb0, const float* __restrict__ sb1,
    const float* __restrict__ M0,  const float* __restrict__ M1,
    const float* __restrict__ M2)
{
    int idx = blockIdx.x*blockDim.x + threadIdx.x;
    if (idx < 16384){
        int pair = idx >> 9, j = idx & 511;
        int l = pair >> 1, net = pair & 1;
        if (j < 256){
            g_B[pair*512 + rank256(j)] = (net ? sb0 : lb0)[l*NHID + j];
        } else {
            int jj = j - 256;
            g_B[pair*512 + 256 + rank256(jj)] = (net ? sb1 : lb1)[l*NHID + jj];
        }
        return;
    }
    int t = idx - 16384;
    if (t < 32768){
        int par = t >> 14, r = t & 16383;
        int n = r >> 6, k = r & 63;
        if (M0[par*W0_SZ + n*64 + k] != 0.f){
            int bit = (k >> 4)*16 + (rank256(n) >> 4);
            atomicOr(&g_act0[par][bit >> 5], 1u << (bit & 31));
        }
        return;
    }
    t -= 32768;
    if (t < 65536){
        int n = t >> 8, k = t & 255;
        if (M1[n*256 + k] != 0.f){
            int bit = (rank256(k) >> 4)*16 + (rank256(n) >> 4);
            atomicOr(&g_act1[bit >> 5], 1u << (bit & 31));
        }
        return;
    }
    t -= 65536;
    {
        int par = t >> 14, r = t & 16383;
        int n = r >> 8, k = r & 255;
        if (M2[par*W2_SZ + n*256 + k] != 0.f){
            int v = par ? 63 - n : n;
            int bit = (rank256(k) >> 4)*8 + (v >> 3);
            atomicOr(&g_act2[par][bit >> 5], 1u << (bit & 31));
        }
    }
}

// ---------- compact: build sorted block lists + slot maps (1 thread) ---------
__global__ void compact_kernel()
{
    if (threadIdx.x || blockIdx.x) return;
    for (int wn = 0; wn < 4; wn++){
        int pos = 0, top = 63;
        for (int g = 0; g < 4; g++){
            int band = (int)((PARTPACK >> ((wn*4+g)*4)) & 15);
            int c = 0;
            for (int kc = 0; kc < 16; kc++){
                int bit = kc*16 + band, idx = kc*4 + g;
                if ((g_act1[bit>>5] >> (bit&31)) & 1){
                    g_list1[wn][pos] = (u8)(kc | (g<<6));
                    g_slot1[wn][idx] = (u8)pos; pos++; c++;
                } else g_slot1[wn][idx] = (u8)(top--);
            }
            g_n1[wn][g] = (u8)c;
        }
        for (int par = 0; par < 2; par++){
            pos = 0; top = 15;
            for (int g = 0; g < 4; g++){
                int band = (int)((PARTPACK >> ((wn*4+g)*4)) & 15);
                int c = 0;
                for (int kc = 0; kc < 4; kc++){
                    int bit = kc*16 + band, idx = kc*4 + g;
                    if ((g_act0[par][bit>>5] >> (bit&31)) & 1){
                        g_list0[par][wn][pos] = (u8)(kc | (g<<6));
                        g_slot0[par][wn][idx] = (u8)pos; pos++; c++;
                    } else g_slot0[par][wn][idx] = (u8)(top--);
                }
                g_n0[par][wn][g] = (u8)c;
            }
            pos = 0; top = 31;
            for (int tt = 0; tt < 2; tt++){
                int B = tt ? 7-wn : wn;
                int c = 0;
                for (int kc = 0; kc < 16; kc++){
                    int bit = kc*8 + B, idx = kc*2 + tt;
                    if ((g_act2[par][bit>>5] >> (bit&31)) & 1){
                        g_list2[par][wn][pos] = (u8)(kc | (tt<<6));
                        g_slot2[par][wn][idx] = (u8)pos; pos++; c++;
                    } else g_slot2[par][wn][idx] = (u8)(top--);
                }
                g_n2[par][wn][tt] = (u8)c;
            }
        }
    }
}

// ---------- prep: mask, bf16 hi/lo split, compacted fragment image -----------
__global__ void prep_kernel(
    const float* __restrict__ lW0, const float* __restrict__ lW1, const float* __restrict__ lW2,
    const float* __restrict__ sW0, const float* __restrict__ sW1, const float* __restrict__ sW2,
    const float* __restrict__ M0,  const float* __restrict__ M1,  const float* __restrict__ M2)
{
    int idx = blockIdx.x*blockDim.x + threadIdx.x;
    if (idx >= 32*WNET) return;
    int pair = idx / WNET, off = idx % WNET;
    int l = pair >> 1, net = pair & 1, par = l & 1;
    float w; int wn, itemoff, lodelta, kl, din;
    if (off < W0_SZ){
        int n = off >> 6, k = off & 63;
        int s = l*W0_SZ + off;
        w = (net ? sW0[s] : lW0[s]) * M0[s];
        int nr = rank256(n); int band = nr >> 4;
        wn = (int)((WNOFPACK >> (band*4)) & 15);
        int g = band >> 2;
        int nn = nr & 15, tt = nn >> 3, nrow = nn & 7;
        int kc = k >> 4; kl = k & 15;
        int slot = g_slot0[par][wn][kc*4+g];
        itemoff = slot*1024; lodelta = 512;
        int T = (nrow << 2) | ((kl & 7) >> 1);
        int b = (tt << 1) | (kl >> 3);
        din = T*16 + b*4 + ((kl & 1) << 1);
    } else if (off < W0_SZ + W1_SZ){
        int o = off - W0_SZ;
        int n = o >> 8, k = o & 255;
        int s = l*W1_SZ + o;
        w = (net ? sW1[s] : lW1[s]) * M1[s];
        int nr = rank256(n); int band = nr >> 4;
        wn = (int)((WNOFPACK >> (band*4)) & 15);
        int g = band >> 2;
        int nn = nr & 15, tt = nn >> 3, nrow = nn & 7;
        int kr = rank256(k);
        int kc = kr >> 4; kl = kr & 15;
        int slot = g_slot1[wn][kc*4+g];
        itemoff = 16384 + slot*1024; lodelta = 512;
        int T = (nrow << 2) | ((kl & 7) >> 1);
        int b = (tt << 1) | (kl >> 3);
        din = T*16 + b*4 + ((kl & 1) << 1);
    } else {
        int o = off - W0_SZ - W1_SZ;
        int n = o >> 8, k = o & 255;
        int s = l*W2_SZ + o;
        w = (net ? sW2[s] : lW2[s]) * M2[s];
        int v = par ? 63 - n : n;
        int B = v >> 3;
        wn = (B < 4) ? B : 7 - B;
        int tt = (B < 4) ? 0 : 1;
        int nrow = v & 7;
        int kr = rank256(k);
        int kc = kr >> 4; kl = kr & 15;
        int slot = g_slot2[par][wn][kc*2+tt];
        itemoff = 81920 + slot*512; lodelta = 256;
        int T = (nrow << 2) | ((kl & 7) >> 1);
        din = T*8 + (kl >> 3)*4 + ((kl & 1) << 1);
    }
    size_t dst = (size_t)wn*GRP_STRIDE + (size_t)pair*GRP_PAIR + itemoff + din;
    __nv_bfloat16 hv = __float2bfloat16_rn(w);
    __nv_bfloat16 lv = __float2bfloat16_rn(w - __bfloat162float(hv));
    *(__nv_bfloat16*)(g_W + dst) = hv;
    *(__nv_bfloat16*)(g_W + dst + lodelta) = lv;
}

// ---------------- fused flow kernel ------------------------------------------
__global__ void __launch_bounds__(NTHREADS,4) flow_kernel(
    const float* __restrict__ u,
    const float* __restrict__ lb2, const float* __restrict__ sb2,
    float* __restrict__ out)
{
    extern __shared__ unsigned char smp[];
    u32 smb = s2u(smp);
    int tid = threadIdx.x, lane = tid & 31, wn = tid >> 5;
    int q = lane >> 3, ln = lane & 7;
    int row0 = blockIdx.x * TBR;
    float* loc_sm = (float*)(smp + SM_LOC);
    float* y_sm   = (float*)(smp + SM_Y);

    int r0 = lane >> 2;
    int lc2 = (lane & 3)*2;

    const unsigned char* tb  = g_W + (size_t)wn*GRP_STRIDE + (size_t)lane*16;
    const unsigned char* tb2 = g_W + (size_t)wn*GRP_STRIDE + (size_t)lane*8;

    #pragma unroll
    for (int i = 0; i < 2; i++)
      #pragma unroll
      for (int j = 0; j < 2; j++)
        #pragma unroll
        for (int rr = 0; rr < 2; rr++){
          int row = r0 + i*16 + rr*8;
          int c = wn*16 + j*8 + lc2;
          float2 v = *(const float2*)(u + (size_t)(row0 + row)*DIM + c);
          *(float2*)&y_sm[row*66 + c] = v;
          writeA2(smp, row, c, v.x, v.y);
        }
    __syncthreads();

    u32 nn1 = *(const u32*)&g_n1[wn][0];
    const u8* l1p = &g_list1[wn][0];

    float acc[16][4];
    auto zacc = [&](){
        #pragma unroll
        for (int t = 0; t < 16; t++){ acc[t][0]=0.f; acc[t][1]=0.f; acc[t][2]=0.f; acc[t][3]=0.f; }
    };
    auto ldA = [&](u32 base, int kc, u32 (*r)[4]){
        u32 arow0 = (u32)(((q & 1) << 3) + ln);
        u32 aunit = (u32)(kc*2 + (q >> 1));
        #pragma unroll
        for (int i = 0; i < 2; i++){
            u32 rr = arow0 + (u32)i*16u;
            u32 aoff = rr*512u + ((aunit ^ (rr & 7u)) << 4);
            ldsm4(r[i], base + aoff);
        }
    };

    #pragma unroll 1
    for (int pair = 0; pair < 32; pair++){
        int l = pair >> 1, net = pair & 1, par = l & 1;
        const float* Bs0 = g_B + pair*512;
        const float* Bs1 = Bs0 + 256;
        const float* b2 = (net ? sb2 : lb2) + l*DIM;
        const unsigned char* wp0 = tb  + (size_t)pair*GRP_PAIR;
        const unsigned char* wp2 = tb2 + (size_t)pair*GRP_PAIR + 81920;
        const u8* l0p = &g_list0[par][wn][0];
        const u8* l2p = &g_list2[par][wn][0];
        u32 nn0 = *(const u32*)&g_n0[par][wn][0];
        unsigned short nn2 = *(const unsigned short*)&g_n2[par][wn][0];

        // preload item 0 of stage0 (both halves)
        uint4 bh4 = *(const uint4*)(wp0);
        uint4 bl4 = *(const uint4*)(wp0 + 512);
        u32 ent = l0p[0];

        // ---- stage0 (compacted, sorted by g) ----
        zacc();
        {
            int itb = 0;
            #pragma unroll
            for (int g = 0; g < 4; g++){
                int cnt = (int)((nn0 >> (g*8)) & 255u);
                #pragma unroll 1
                for (int t = 0; t < cnt; t++){
                    int it = itb + t;
                    // prefetch item t+1 (both halves) at top — full item to cover latency
                    uint4 bhn = *(const uint4*)(wp0 + (it+1)*1024);
                    uint4 bln = *(const uint4*)(wp0 + (it+1)*1024 + 512);
                    int kc = (int)(ent & 15u);
                    u32 ah[2][4], al[2][4];
                    ldA(smb + SM_AHI, kc, ah);
                    ldA(smb + SM_ALO, kc, al);
                    u32 bc[4] = {bh4.x, bh4.y, bh4.z, bh4.w};
                    u32 bd[4] = {bl4.x, bl4.y, bl4.z, bl4.w};
                    ent = l0p[it+1];
                    #pragma unroll
                    for (int i = 0; i < 2; i++)
                      #pragma unroll
                      for (int tt = 0; tt < 2; tt++)
                        mma_bf16(acc[i*8 + g*2 + tt], ah[i], bc + tt*2);
                    #pragma unroll
                    for (int i = 0; i < 2; i++)
                      #pragma unroll
                      for (int tt = 0; tt < 2; tt++)
                        mma_bf16(acc[i*8 + g*2 + tt], al[i], bc + tt*2);
                    #pragma unroll
                    for (int i = 0; i < 2; i++)
                      #pragma unroll
                      for (int tt = 0; tt < 2; tt++)
                        mma_bf16(acc[i*8 + g*2 + tt], ah[i], bd + tt*2);
                    bh4 = bhn; bl4 = bln;
                }
                itb += cnt;
            }
        }
        // prefetch stage1 head (both halves)
        bh4 = *(const uint4*)(wp0 + 16384);
        bl4 = *(const uint4*)(wp0 + 16384 + 512);
        ent = l1p[0];
        __syncthreads();
        #pragma unroll
        for (int i = 0; i < 2; i++)
          #pragma unroll
          for (int j = 0; j < 8; j++){
            int g = j >> 1, tt = j & 1;
            int band = (int)((PARTPACK >> ((wn*4+g)*4)) & 15);
            int c = band*16 + tt*8 + lc2;
            float2 bb = *(const float2*)(Bs0 + c);
            float* d = acc[i*8 + j];
            writeA2(smp, r0 + i*16,     c, fmaxf(d[0]+bb.x,0.f), fmaxf(d[1]+bb.y,0.f));
            writeA2(smp, r0 + i*16 + 8, c, fmaxf(d[2]+bb.x,0.f), fmaxf(d[3]+bb.y,0.f));
          }
        __syncthreads();

        // ---- stage1 (compacted) ----
        zacc();
        {
            const unsigned char* w1 = wp0 + 16384;
            int itb = 0;
            #pragma unroll
            for (int g = 0; g < 4; g++){
                int cnt = (int)((nn1 >> (g*8)) & 255u);
                #pragma unroll 1
                for (int t = 0; t < cnt; t++){
                    int it = itb + t;
                    uint4 bhn = *(const uint4*)(w1 + (it+1)*1024);
                    uint4 bln = *(const uint4*)(w1 + (it+1)*1024 + 512);
                    int kc = (int)(ent & 15u);
                    u32 ah[2][4], al[2][4];
                    ldA(smb + SM_AHI, kc, ah);
                    ldA(smb + SM_ALO, kc, al);
                    u32 bc[4] = {bh4.x, bh4.y, bh4.z, bh4.w};
                    u32 bd[4] = {bl4.x, bl4.y, bl4.z, bl4.w};
                    ent = l1p[it+1];
                    #pragma unroll
                    for (int i = 0; i < 2; i++)
                      #pragma unroll
                      for (int tt = 0; tt < 2; tt++)
                        mma_bf16(acc[i*8 + g*2 + tt], ah[i], bc + tt*2);
                    #pragma unroll
                    for (int i = 0; i < 2; i++)
                      #pragma unroll
                      for (int tt = 0; tt < 2; tt++)
                        mma_bf16(acc[i*8 + g*2 + tt], al[i], bc + tt*2);
                    #pragma unroll
                    for (int i = 0; i < 2; i++)
                      #pragma unroll
                      for (int tt = 0; tt < 2; tt++)
                        mma_bf16(acc[i*8 + g*2 + tt], ah[i], bd + tt*2);
                    bh4 = bhn; bl4 = bln;
                }
                itb += cnt;
            }
        }
        // prefetch stage2 head (both halves)
        uint2 bh2 = *(const uint2*)(wp2);
        uint2 bl2 = *(const uint2*)(wp2 + 256);
        u32 ent2 = l2p[0];
        __syncthreads();
        #pragma unroll
        for (int i = 0; i < 2; i++)
          #pragma unroll
          for (int j = 0; j < 8; j++){
            int g = j >> 1, tt = j & 1;
            int band = (int)((PARTPACK >> ((wn*4+g)*4)) & 15);
            int c = band*16 + tt*8 + lc2;
            float2 bb = *(const float2*)(Bs1 + c);
            float* d = acc[i*8 + j];
            writeA2(smp, r0 + i*16,     c, fmaxf(d[0]+bb.x,0.f), fmaxf(d[1]+bb.y,0.f));
            writeA2(smp, r0 + i*16 + 8, c, fmaxf(d[2]+bb.x,0.f), fmaxf(d[3]+bb.y,0.f));
          }
        __syncthreads();

        // ---- stage2 (compacted, sorted by tt) ----
        zacc();
        {
            int itb = 0;
            #pragma unroll
            for (int tt = 0; tt < 2; tt++){
                int cnt = (int)((nn2 >> (tt*8)) & 255u);
                #pragma unroll 1
                for (int t = 0; t < cnt; t++){
                    int it = itb + t;
                    uint2 bhn = *(const uint2*)(wp2 + (it+1)*512);
                    uint2 bln = *(const uint2*)(wp2 + (it+1)*512 + 256);
                    int kc = (int)(ent2 & 15u);
                    u32 ah[2][4], al[2][4];
                    ldA(smb + SM_AHI, kc, ah);
                    ldA(smb + SM_ALO, kc, al);
                    u32 bc[2] = {bh2.x, bh2.y};
                    u32 bd[2] = {bl2.x, bl2.y};
                    ent2 = l2p[it+1];
                    #pragma unroll
                    for (int i = 0; i < 2; i++)
                        mma_bf16(acc[i*8 + tt], ah[i], bc);
                    #pragma unroll
                    for (int i = 0; i < 2; i++)
                        mma_bf16(acc[i*8 + tt], al[i], bc);
                    #pragma unroll
                    for (int i = 0; i < 2; i++)
                        mma_bf16(acc[i*8 + tt], ah[i], bd);
                    bh2 = bhn; bl2 = bln;
                }
                itb += cnt;
            }
        }
        __syncthreads();
        #pragma unroll
        for (int i = 0; i < 2; i++)
          #pragma unroll
          for (int j = 0; j < 2; j++){
            int Bsel = j ? 7-wn : wn;
            int v = Bsel*8 + lc2;
            int f0 = par ? 63-v : v;
            int f1 = par ? 62-v : v+1;
            float bb0 = b2[f0], bb1 = b2[f1];
            float* d = acc[i*8 + j];
            #pragma unroll
            for (int rr = 0; rr < 2; rr++){
                int row = r0 + i*16 + rr*8;
                float s0 = d[rr*2]   + bb0;
                float s1 = d[rr*2+1] + bb1;
                if (net == 0){
                    loc_sm[row*66 + f0] = s0;
                    loc_sm[row*66 + f1] = s1;
                    int ce = par ? 62-v : v;
                    float ya = y_sm[row*66 + ce];
                    float yb = y_sm[row*66 + ce + 1];
                    writeA2(smp, row, ce, ya, yb);
                } else {
                    float y0 = expf(-s0) * (y_sm[row*66 + f0] - loc_sm[row*66 + f0]);
                    float y1 = expf(-s1) * (y_sm[row*66 + f1] - loc_sm[row*66 + f1]);
                    int ce = par ? 62-v : v;
                    float ca = par ? y1 : y0;
                    float cbv = par ? y0 : y1;
                    if (pair == 31){
                        *(float2*)(out + (size_t)(row0 + row)*DIM + ce) = make_float2(ca, cbv);
                    } else {
                        y_sm[row*66 + ce]     = ca;
                        y_sm[row*66 + ce + 1] = cbv;
                        writeA2(smp, row, ce, ca, cbv);
                    }
                }
            }
          }
        __syncthreads();
    }
}

// ---------------- launch ------------------------------------------------------
extern "C" void kernel_launch(void* const* d_in, const int* in_sizes, int n_in,
                              void* d_out, int out_size)
{
    const float* u   = (const float*)d_in[0];
    const float* lW0 = (const float*)d_in[1];
    const float* lb0 = (const float*)d_in[2];
    const float* lW1 = (const float*)d_in[3];
    const float* lb1 = (const float*)d_in[4];
    const float* lW2 = (const float*)d_in[5];
    const float* lb2 = (const float*)d_in[6];
    const float* sW0 = (const float*)d_in[7];
    const float* sb0 = (const float*)d_in[8];
    const float* sW1 = (const float*)d_in[9];
    const float* sb1 = (const float*)d_in[10];
    const float* sW2 = (const float*)d_in[11];
    const float* sb2 = (const float*)d_in[12];
    const float* M0  = (const float*)d_in[13];
    const float* M1  = (const float*)d_in[14];
    const float* M2  = (const float*)d_in[15];

    int rows = in_sizes[0] / DIM;

    cudaFuncSetAttribute(flow_kernel, cudaFuncAttributeMaxDynamicSharedMemorySize, SM_TOTAL);

    meta_kernel<<<(147456 + 255)/256, 256>>>(lb0, lb1, sb0, sb1, M0, M1, M2);
    compact_kernel<<<1, 32>>>();
    const int total = 32*WNET;
    prep_kernel<<<(total + 255)/256, 256>>>(lW0, lW1, lW2, sW0, sW1, sW2, M0, M1, M2);

    flow_kernel<<<rows / TBR, NTHREADS, SM_TOTAL>>>(u, lb2, sb2, (float*)d_out);
}